// round 5
// baseline (speedup 1.0000x reference)
#include <cuda_runtime.h>

#define B_   1024
#define D_   64
#define H_   256
#define G4   1024      // 4*H
#define T_   128
#define A_   8
#define GRID 148       // CTAs for main kernel (<= SM count; balanced 6/7 rows)

// ----------------- static device scratch (no allocations allowed) ----------
// packed weights: [kpair][j][gate][e] , e = k parity  (8 floats per (kpair,j))
__device__ float g_WT0p[128 * H_ * 8];        // W_hh0^T packed   (1 MB)
__device__ float g_WT1p[256 * H_ * 8];        // [W_ih1;W_hh1]^T packed (2 MB)
__device__ float g_b1[G4];                    // (b_ih1+b_hh1) as [j][gate]
__device__ float g_gx0[B_ * G4];              // xn@W_ih0^T + b0, as [b][j][gate]

typedef unsigned long long u64;

// ----------------- packed f32x2 helpers (sm_103a FFMA2) --------------------
__device__ __forceinline__ u64 ffma2(u64 a, u64 b, u64 c) {
    u64 d;
    asm("fma.rn.f32x2 %0, %1, %2, %3;" : "=l"(d) : "l"(a), "l"(b), "l"(c));
    return d;
}
__device__ __forceinline__ float hadd2(u64 v) {
    float lo, hi;
    asm("mov.b64 {%0, %1}, %2;" : "=f"(lo), "=f"(hi) : "l"(v));
    return lo + hi;
}

// ----------------- activations (fp32, ~1e-7 rel) ---------------------------
__device__ __forceinline__ float sigf(float x) {
    return __fdividef(1.0f, 1.0f + __expf(-x));
}
__device__ __forceinline__ float tanhf_(float x) {
    return 1.0f - __fdividef(2.0f, __expf(2.0f * x) + 1.0f);
}

// ============================================================================
// Prep 1: repack recurrent weights into [kpair][j][gate][e], fold L1 biases
// ============================================================================
__global__ void prep_weights(const float* __restrict__ Whh0,
                             const float* __restrict__ Wih1,
                             const float* __restrict__ Whh1,
                             const float* __restrict__ bih1,
                             const float* __restrict__ bhh1)
{
    const int idx = blockIdx.x * blockDim.x + threadIdx.x;
    const int stride = gridDim.x * blockDim.x;
    for (int i = idx; i < 128 * H_ * 8; i += stride) {
        const int e = i & 1, g = (i >> 1) & 3, j = (i >> 3) & (H_ - 1), p = i >> 11;
        const int k = 2 * p + e;
        g_WT0p[i] = Whh0[(g * H_ + j) * H_ + k];
    }
    for (int i = idx; i < 256 * H_ * 8; i += stride) {
        const int e = i & 1, g = (i >> 1) & 3, j = (i >> 3) & (H_ - 1), p = i >> 11;
        const int k = 2 * p + e;
        const int n = g * H_ + j;
        g_WT1p[i] = (k < H_) ? Wih1[n * H_ + k] : Whh1[n * H_ + (k - H_)];
    }
    for (int i = idx; i < G4; i += stride) {
        const int g = i & 3, j = i >> 2;
        g_b1[i] = bih1[g * H_ + j] + bhh1[g * H_ + j];
    }
}

// ============================================================================
// Prep 2: layernorm(state) then gx0 = xn @ W_ih0^T + (b_ih0 + b_hh0)
// ============================================================================
__global__ void prep_gx0(const float* __restrict__ state,
                         const float* __restrict__ gamma,
                         const float* __restrict__ beta,
                         const float* __restrict__ Wih0,
                         const float* __restrict__ bih0,
                         const float* __restrict__ bhh0)
{
    const int b = blockIdx.x;
    const int t = threadIdx.x;
    __shared__ float xs[D_];
    __shared__ float xn[D_];

    if (t < D_) xs[t] = state[b * D_ + t];
    __syncthreads();

    float mu = 0.f;
    #pragma unroll
    for (int k = 0; k < D_; k++) mu += xs[k];
    mu *= (1.0f / D_);
    float var = 0.f;
    #pragma unroll
    for (int k = 0; k < D_; k++) { const float d = xs[k] - mu; var += d * d; }
    var *= (1.0f / D_);
    const float rs = rsqrtf(var + 1e-5f);

    if (t < D_) xn[t] = (xs[t] - mu) * rs * gamma[t] + beta[t];
    __syncthreads();

    #pragma unroll
    for (int g = 0; g < 4; g++) {
        const int n = g * H_ + t;
        const float* w = Wih0 + n * D_;
        float acc = bih0[n] + bhh0[n];
        #pragma unroll
        for (int k = 0; k < D_; k++) acc += xn[k] * w[k];
        g_gx0[(b * H_ + t) * 4 + g] = acc;
    }
}

// ============================================================================
// Main recurrence. GRID CTAs x 256 threads; CTA owns MBT (6 or 7) batch rows,
// thread t owns hidden index j=t of both layers. c-states stay in registers.
// f32x2 lanes = even/odd-k partial sums; h in plain-float shared (LDS.64 per
// k-pair per row), weights 32B/thread/kpair coalesced from L2.
// ============================================================================
template <int MBT>
__device__ __forceinline__ void run_lstm(
    const int b0, const int t,
    float (&sh0)[2][7][H_], float (&sh1)[2][7][H_],
    const float* __restrict__ sfc, const float* __restrict__ sfcb,
    float* __restrict__ out)
{
    #pragma unroll
    for (int r = 0; r < MBT; r++) { sh0[0][r][t] = 0.f; sh1[0][r][t] = 0.f; }

    // time-invariant gate biases
    float gx[MBT][4];
    #pragma unroll
    for (int r = 0; r < MBT; r++) {
        const float4 g = *(const float4*)(g_gx0 + ((b0 + r) * H_ + t) * 4);
        gx[r][0] = g.x; gx[r][1] = g.y; gx[r][2] = g.z; gx[r][3] = g.w;
    }
    float b1v[4];
    {
        const float4 g = *(const float4*)(g_b1 + t * 4);
        b1v[0] = g.x; b1v[1] = g.y; b1v[2] = g.z; b1v[3] = g.w;
    }

    float c0[MBT], c1[MBT];
    #pragma unroll
    for (int r = 0; r < MBT; r++) { c0[r] = 0.f; c1[r] = 0.f; }

    __syncthreads();

    const ulonglong2* __restrict__ w0p = ((const ulonglong2*)g_WT0p) + t * 2;
    const ulonglong2* __restrict__ w1p = ((const ulonglong2*)g_WT1p) + t * 2;

    int pb = 0;
    for (int step = 0; step < T_; step++, pb ^= 1) {
        // ---------------- layer 0: h0_old @ W_hh0^T ------------------------
        u64 acc[MBT][4];
        #pragma unroll
        for (int r = 0; r < MBT; r++)
            #pragma unroll
            for (int g = 0; g < 4; g++) acc[r][g] = 0ull;

        #pragma unroll 4
        for (int p = 0; p < 128; p++) {
            const ulonglong2 wA = __ldg(w0p + p * 512);      // gates 0,1
            const ulonglong2 wB = __ldg(w0p + p * 512 + 1);  // gates 2,3
            #pragma unroll
            for (int r = 0; r < MBT; r++) {
                const u64 h2 = *(const u64*)&sh0[pb][r][2 * p];
                acc[r][0] = ffma2(h2, wA.x, acc[r][0]);
                acc[r][1] = ffma2(h2, wA.y, acc[r][1]);
                acc[r][2] = ffma2(h2, wB.x, acc[r][2]);
                acc[r][3] = ffma2(h2, wB.y, acc[r][3]);
            }
        }
        #pragma unroll
        for (int r = 0; r < MBT; r++) {
            const float gi = hadd2(acc[r][0]) + gx[r][0];
            const float gf = hadd2(acc[r][1]) + gx[r][1];
            const float gg = hadd2(acc[r][2]) + gx[r][2];
            const float go = hadd2(acc[r][3]) + gx[r][3];
            const float cn = sigf(gf) * c0[r] + sigf(gi) * tanhf_(gg);
            c0[r] = cn;
            sh0[pb ^ 1][r][t] = sigf(go) * tanhf_(cn);
        }
        __syncthreads();

        // -------- layer 1: h0_new @ W_ih1^T + h1_old @ W_hh1^T --------------
        #pragma unroll
        for (int r = 0; r < MBT; r++)
            #pragma unroll
            for (int g = 0; g < 4; g++) acc[r][g] = 0ull;

        #pragma unroll 4
        for (int p = 0; p < 128; p++) {
            const ulonglong2 wA = __ldg(w1p + p * 512);
            const ulonglong2 wB = __ldg(w1p + p * 512 + 1);
            #pragma unroll
            for (int r = 0; r < MBT; r++) {
                const u64 h2 = *(const u64*)&sh0[pb ^ 1][r][2 * p];
                acc[r][0] = ffma2(h2, wA.x, acc[r][0]);
                acc[r][1] = ffma2(h2, wA.y, acc[r][1]);
                acc[r][2] = ffma2(h2, wB.x, acc[r][2]);
                acc[r][3] = ffma2(h2, wB.y, acc[r][3]);
            }
        }
        #pragma unroll 4
        for (int p = 0; p < 128; p++) {
            const ulonglong2 wA = __ldg(w1p + (128 + p) * 512);
            const ulonglong2 wB = __ldg(w1p + (128 + p) * 512 + 1);
            #pragma unroll
            for (int r = 0; r < MBT; r++) {
                const u64 h2 = *(const u64*)&sh1[pb][r][2 * p];
                acc[r][0] = ffma2(h2, wA.x, acc[r][0]);
                acc[r][1] = ffma2(h2, wA.y, acc[r][1]);
                acc[r][2] = ffma2(h2, wB.x, acc[r][2]);
                acc[r][3] = ffma2(h2, wB.y, acc[r][3]);
            }
        }
        #pragma unroll
        for (int r = 0; r < MBT; r++) {
            const float gi = hadd2(acc[r][0]) + b1v[0];
            const float gf = hadd2(acc[r][1]) + b1v[1];
            const float gg = hadd2(acc[r][2]) + b1v[2];
            const float go = hadd2(acc[r][3]) + b1v[3];
            const float cn = sigf(gf) * c1[r] + sigf(gi) * tanhf_(gg);
            c1[r] = cn;
            sh1[pb ^ 1][r][t] = sigf(go) * tanhf_(cn);
        }
        __syncthreads();

        // ---------------- FC head: tanh(h1 @ fcW^T + fcb) ------------------
        {
            const int row  = t >> 5;
            const int lane = t & 31;
            const int a    = lane >> 2;
            const int part = lane & 3;
            if (row < MBT) {
                const float* hrow = &sh1[pb ^ 1][row][0];
                const float* wrow = sfc + a * H_ + part * 64;
                float accf = 0.f;
                #pragma unroll 8
                for (int jj = 0; jj < 64; jj++)
                    accf += hrow[part * 64 + jj] * wrow[jj];
                accf += __shfl_xor_sync(0xffffffffu, accf, 1);
                accf += __shfl_xor_sync(0xffffffffu, accf, 2);
                if (part == 0)
                    out[((b0 + row) * T_ + step) * A_ + a] =
                        tanhf_(accf + sfcb[a]);
            }
        }
    }
}

__global__ void __launch_bounds__(256, 1)
lstm_main(const float* __restrict__ fcW,
          const float* __restrict__ fcb,
          float* __restrict__ out)
{
    __shared__ float sh0[2][7][H_];
    __shared__ float sh1[2][7][H_];
    __shared__ float sfc[A_ * H_];
    __shared__ float sfcb[A_];

    const int t = threadIdx.x;
    for (int i = t; i < A_ * H_; i += 256) sfc[i] = fcW[i];
    if (t < A_) sfcb[t] = fcb[t];

    const int b0  = (blockIdx.x * B_) / GRID;
    const int cnt = ((blockIdx.x + 1) * B_) / GRID - b0;

    if (cnt == 7) run_lstm<7>(b0, t, sh0, sh1, sfc, sfcb, out);
    else          run_lstm<6>(b0, t, sh0, sh1, sfc, sfcb, out);
}

// ============================================================================
extern "C" void kernel_launch(void* const* d_in, const int* in_sizes, int n_in,
                              void* d_out, int out_size)
{
    const float* state = (const float*)d_in[0];
    const float* gamma = (const float*)d_in[1];
    const float* beta  = (const float*)d_in[2];
    const float* Wih0  = (const float*)d_in[3];
    const float* Whh0  = (const float*)d_in[4];
    const float* bih0  = (const float*)d_in[5];
    const float* bhh0  = (const float*)d_in[6];
    const float* Wih1  = (const float*)d_in[7];
    const float* Whh1  = (const float*)d_in[8];
    const float* bih1  = (const float*)d_in[9];
    const float* bhh1  = (const float*)d_in[10];
    const float* fcW   = (const float*)d_in[11];
    const float* fcb   = (const float*)d_in[12];
    float* out = (float*)d_out;

    prep_weights<<<264, 256>>>(Whh0, Wih1, Whh1, bih1, bhh1);
    prep_gx0<<<B_, 256>>>(state, gamma, beta, Wih0, bih0, bhh0);
    lstm_main<<<GRID, 256>>>(fcW, fcb, out);
}

// round 6
// speedup vs baseline: 1.0013x; 1.0013x over previous
#include <cuda_runtime.h>

#define B_   1024
#define D_   64
#define H_   256
#define G4   1024      // 4*H
#define T_   128
#define A_   8
#define GRID 148       // CTAs for main kernel (<= SM count; balanced 6/7 rows)

// ----------------- static device scratch (no allocations allowed) ----------
// packed weights: [kpair][j][gate][e] , e = k parity  (8 floats per (kpair,j))
__device__ float g_WT0p[128 * H_ * 8];        // W_hh0^T packed   (1 MB)
__device__ float g_WT1p[256 * H_ * 8];        // [W_ih1;W_hh1]^T packed (2 MB)
__device__ float g_b1[G4];                    // (b_ih1+b_hh1) as [j][gate]
__device__ float g_gx0[B_ * G4];              // xn@W_ih0^T + b0, as [b][j][gate]

typedef unsigned long long u64;

// ----------------- packed f32x2 helpers (sm_103a FFMA2) --------------------
__device__ __forceinline__ u64 ffma2(u64 a, u64 b, u64 c) {
    u64 d;
    asm("fma.rn.f32x2 %0, %1, %2, %3;" : "=l"(d) : "l"(a), "l"(b), "l"(c));
    return d;
}
__device__ __forceinline__ float hadd2(u64 v) {
    float lo, hi;
    asm("mov.b64 {%0, %1}, %2;" : "=f"(lo), "=f"(hi) : "l"(v));
    return lo + hi;
}

// ----------------- activations (fp32, ~1e-7 rel) ---------------------------
__device__ __forceinline__ float sigf(float x) {
    return __fdividef(1.0f, 1.0f + __expf(-x));
}
__device__ __forceinline__ float tanhf_(float x) {
    return 1.0f - __fdividef(2.0f, __expf(2.0f * x) + 1.0f);
}

// ============================================================================
// Prep 1: repack recurrent weights into [kpair][j][gate][e], fold L1 biases
// ============================================================================
__global__ void prep_weights(const float* __restrict__ Whh0,
                             const float* __restrict__ Wih1,
                             const float* __restrict__ Whh1,
                             const float* __restrict__ bih1,
                             const float* __restrict__ bhh1)
{
    const int idx = blockIdx.x * blockDim.x + threadIdx.x;
    const int stride = gridDim.x * blockDim.x;
    for (int i = idx; i < 128 * H_ * 8; i += stride) {
        const int e = i & 1, g = (i >> 1) & 3, j = (i >> 3) & (H_ - 1), p = i >> 11;
        const int k = 2 * p + e;
        g_WT0p[i] = Whh0[(g * H_ + j) * H_ + k];
    }
    for (int i = idx; i < 256 * H_ * 8; i += stride) {
        const int e = i & 1, g = (i >> 1) & 3, j = (i >> 3) & (H_ - 1), p = i >> 11;
        const int k = 2 * p + e;
        const int n = g * H_ + j;
        g_WT1p[i] = (k < H_) ? Wih1[n * H_ + k] : Whh1[n * H_ + (k - H_)];
    }
    for (int i = idx; i < G4; i += stride) {
        const int g = i & 3, j = i >> 2;
        g_b1[i] = bih1[g * H_ + j] + bhh1[g * H_ + j];
    }
}

// ============================================================================
// Prep 2: layernorm(state) then gx0 = xn @ W_ih0^T + (b_ih0 + b_hh0)
// ============================================================================
__global__ void prep_gx0(const float* __restrict__ state,
                         const float* __restrict__ gamma,
                         const float* __restrict__ beta,
                         const float* __restrict__ Wih0,
                         const float* __restrict__ bih0,
                         const float* __restrict__ bhh0)
{
    const int b = blockIdx.x;
    const int t = threadIdx.x;
    __shared__ float xs[D_];
    __shared__ float xn[D_];

    if (t < D_) xs[t] = state[b * D_ + t];
    __syncthreads();

    float mu = 0.f;
    #pragma unroll
    for (int k = 0; k < D_; k++) mu += xs[k];
    mu *= (1.0f / D_);
    float var = 0.f;
    #pragma unroll
    for (int k = 0; k < D_; k++) { const float d = xs[k] - mu; var += d * d; }
    var *= (1.0f / D_);
    const float rs = rsqrtf(var + 1e-5f);

    if (t < D_) xn[t] = (xs[t] - mu) * rs * gamma[t] + beta[t];
    __syncthreads();

    #pragma unroll
    for (int g = 0; g < 4; g++) {
        const int n = g * H_ + t;
        const float* w = Wih0 + n * D_;
        float acc = bih0[n] + bhh0[n];
        #pragma unroll
        for (int k = 0; k < D_; k++) acc += xn[k] * w[k];
        g_gx0[(b * H_ + t) * 4 + g] = acc;
    }
}

// ============================================================================
// Main recurrence. GRID CTAs x 256 threads; CTA owns MBT (6 or 7) batch rows,
// thread t owns hidden index j=t of both layers. c-states stay in registers.
// f32x2 lanes = even/odd-k partial sums; h in plain-float shared (LDS.64 per
// k-pair per row), weights 32B/thread/kpair coalesced from L2.
// ============================================================================
template <int MBT>
__device__ __forceinline__ void run_lstm(
    const int b0, const int t,
    float (&sh0)[2][7][H_], float (&sh1)[2][7][H_],
    const float* __restrict__ sfc, const float* __restrict__ sfcb,
    float* __restrict__ out)
{
    #pragma unroll
    for (int r = 0; r < MBT; r++) { sh0[0][r][t] = 0.f; sh1[0][r][t] = 0.f; }

    // time-invariant gate biases
    float gx[MBT][4];
    #pragma unroll
    for (int r = 0; r < MBT; r++) {
        const float4 g = *(const float4*)(g_gx0 + ((b0 + r) * H_ + t) * 4);
        gx[r][0] = g.x; gx[r][1] = g.y; gx[r][2] = g.z; gx[r][3] = g.w;
    }
    float b1v[4];
    {
        const float4 g = *(const float4*)(g_b1 + t * 4);
        b1v[0] = g.x; b1v[1] = g.y; b1v[2] = g.z; b1v[3] = g.w;
    }

    float c0[MBT], c1[MBT];
    #pragma unroll
    for (int r = 0; r < MBT; r++) { c0[r] = 0.f; c1[r] = 0.f; }

    __syncthreads();

    const ulonglong2* __restrict__ w0p = ((const ulonglong2*)g_WT0p) + t * 2;
    const ulonglong2* __restrict__ w1p = ((const ulonglong2*)g_WT1p) + t * 2;

    int pb = 0;
    for (int step = 0; step < T_; step++, pb ^= 1) {
        // ---------------- layer 0: h0_old @ W_hh0^T ------------------------
        u64 acc[MBT][4];
        #pragma unroll
        for (int r = 0; r < MBT; r++)
            #pragma unroll
            for (int g = 0; g < 4; g++) acc[r][g] = 0ull;

        #pragma unroll 4
        for (int p = 0; p < 128; p++) {
            const ulonglong2 wA = __ldg(w0p + p * 512);      // gates 0,1
            const ulonglong2 wB = __ldg(w0p + p * 512 + 1);  // gates 2,3
            #pragma unroll
            for (int r = 0; r < MBT; r++) {
                const u64 h2 = *(const u64*)&sh0[pb][r][2 * p];
                acc[r][0] = ffma2(h2, wA.x, acc[r][0]);
                acc[r][1] = ffma2(h2, wA.y, acc[r][1]);
                acc[r][2] = ffma2(h2, wB.x, acc[r][2]);
                acc[r][3] = ffma2(h2, wB.y, acc[r][3]);
            }
        }
        #pragma unroll
        for (int r = 0; r < MBT; r++) {
            const float gi = hadd2(acc[r][0]) + gx[r][0];
            const float gf = hadd2(acc[r][1]) + gx[r][1];
            const float gg = hadd2(acc[r][2]) + gx[r][2];
            const float go = hadd2(acc[r][3]) + gx[r][3];
            const float cn = sigf(gf) * c0[r] + sigf(gi) * tanhf_(gg);
            c0[r] = cn;
            sh0[pb ^ 1][r][t] = sigf(go) * tanhf_(cn);
        }
        __syncthreads();

        // -------- layer 1: h0_new @ W_ih1^T + h1_old @ W_hh1^T --------------
        #pragma unroll
        for (int r = 0; r < MBT; r++)
            #pragma unroll
            for (int g = 0; g < 4; g++) acc[r][g] = 0ull;

        #pragma unroll 4
        for (int p = 0; p < 128; p++) {
            const ulonglong2 wA = __ldg(w1p + p * 512);
            const ulonglong2 wB = __ldg(w1p + p * 512 + 1);
            #pragma unroll
            for (int r = 0; r < MBT; r++) {
                const u64 h2 = *(const u64*)&sh0[pb ^ 1][r][2 * p];
                acc[r][0] = ffma2(h2, wA.x, acc[r][0]);
                acc[r][1] = ffma2(h2, wA.y, acc[r][1]);
                acc[r][2] = ffma2(h2, wB.x, acc[r][2]);
                acc[r][3] = ffma2(h2, wB.y, acc[r][3]);
            }
        }
        #pragma unroll 4
        for (int p = 0; p < 128; p++) {
            const ulonglong2 wA = __ldg(w1p + (128 + p) * 512);
            const ulonglong2 wB = __ldg(w1p + (128 + p) * 512 + 1);
            #pragma unroll
            for (int r = 0; r < MBT; r++) {
                const u64 h2 = *(const u64*)&sh1[pb][r][2 * p];
                acc[r][0] = ffma2(h2, wA.x, acc[r][0]);
                acc[r][1] = ffma2(h2, wA.y, acc[r][1]);
                acc[r][2] = ffma2(h2, wB.x, acc[r][2]);
                acc[r][3] = ffma2(h2, wB.y, acc[r][3]);
            }
        }
        #pragma unroll
        for (int r = 0; r < MBT; r++) {
            const float gi = hadd2(acc[r][0]) + b1v[0];
            const float gf = hadd2(acc[r][1]) + b1v[1];
            const float gg = hadd2(acc[r][2]) + b1v[2];
            const float go = hadd2(acc[r][3]) + b1v[3];
            const float cn = sigf(gf) * c1[r] + sigf(gi) * tanhf_(gg);
            c1[r] = cn;
            sh1[pb ^ 1][r][t] = sigf(go) * tanhf_(cn);
        }
        __syncthreads();

        // ---------------- FC head: tanh(h1 @ fcW^T + fcb) ------------------
        {
            const int row  = t >> 5;
            const int lane = t & 31;
            const int a    = lane >> 2;
            const int part = lane & 3;
            if (row < MBT) {
                const float* hrow = &sh1[pb ^ 1][row][0];
                const float* wrow = sfc + a * H_ + part * 64;
                float accf = 0.f;
                #pragma unroll 8
                for (int jj = 0; jj < 64; jj++)
                    accf += hrow[part * 64 + jj] * wrow[jj];
                accf += __shfl_xor_sync(0xffffffffu, accf, 1);
                accf += __shfl_xor_sync(0xffffffffu, accf, 2);
                if (part == 0)
                    out[((b0 + row) * T_ + step) * A_ + a] =
                        tanhf_(accf + sfcb[a]);
            }
        }
    }
}

__global__ void __launch_bounds__(256, 1)
lstm_main(const float* __restrict__ fcW,
          const float* __restrict__ fcb,
          float* __restrict__ out)
{
    __shared__ float sh0[2][7][H_];
    __shared__ float sh1[2][7][H_];
    __shared__ float sfc[A_ * H_];
    __shared__ float sfcb[A_];

    const int t = threadIdx.x;
    for (int i = t; i < A_ * H_; i += 256) sfc[i] = fcW[i];
    if (t < A_) sfcb[t] = fcb[t];

    const int b0  = (blockIdx.x * B_) / GRID;
    const int cnt = ((blockIdx.x + 1) * B_) / GRID - b0;

    if (cnt == 7) run_lstm<7>(b0, t, sh0, sh1, sfc, sfcb, out);
    else          run_lstm<6>(b0, t, sh0, sh1, sfc, sfcb, out);
}

// ============================================================================
extern "C" void kernel_launch(void* const* d_in, const int* in_sizes, int n_in,
                              void* d_out, int out_size)
{
    const float* state = (const float*)d_in[0];
    const float* gamma = (const float*)d_in[1];
    const float* beta  = (const float*)d_in[2];
    const float* Wih0  = (const float*)d_in[3];
    const float* Whh0  = (const float*)d_in[4];
    const float* bih0  = (const float*)d_in[5];
    const float* bhh0  = (const float*)d_in[6];
    const float* Wih1  = (const float*)d_in[7];
    const float* Whh1  = (const float*)d_in[8];
    const float* bih1  = (const float*)d_in[9];
    const float* bhh1  = (const float*)d_in[10];
    const float* fcW   = (const float*)d_in[11];
    const float* fcb   = (const float*)d_in[12];
    float* out = (float*)d_out;

    prep_weights<<<264, 256>>>(Whh0, Wih1, Whh1, bih1, bhh1);
    prep_gx0<<<B_, 256>>>(state, gamma, beta, Wih0, bih0, bhh0);
    lstm_main<<<GRID, 256>>>(fcW, fcb, out);
}

// round 7
// speedup vs baseline: 1.0662x; 1.0648x over previous
#include <cuda_runtime.h>

#define B_    1024
#define D_    64
#define H_    256
#define G4    1024       // 4*H
#define T_    128
#define A_    8
#define NCL   74         // clusters
#define GRID  148        // 74 clusters * 2 CTAs
#define MBT   14         // batch rows per cluster (padded; real 13 or 14)
#define HS    132        // padded row stride for h arrays (floats)

// ----------------- static device scratch (no allocations allowed) ----------
// packed weights: [kpair][j][gate][e] , e = k parity  (8 floats per (kpair,j))
__device__ float g_WT0p[128 * H_ * 8];        // W_hh0^T packed   (1 MB)
__device__ float g_WT1p[256 * H_ * 8];        // [W_ih1;W_hh1]^T packed (2 MB)
__device__ float g_b1[G4];                    // (b_ih1+b_hh1) as [j][gate]
__device__ float g_gx0[B_ * G4];              // xn@W_ih0^T + b0, as [b][j][gate]

typedef unsigned long long u64;

// ----------------- packed f32x2 helpers (sm_103a FFMA2) --------------------
__device__ __forceinline__ u64 ffma2(u64 a, u64 b, u64 c) {
    u64 d;
    asm("fma.rn.f32x2 %0, %1, %2, %3;" : "=l"(d) : "l"(a), "l"(b), "l"(c));
    return d;
}
__device__ __forceinline__ float hadd2(u64 v) {
    float lo, hi;
    asm("mov.b64 {%0, %1}, %2;" : "=f"(lo), "=f"(hi) : "l"(v));
    return lo + hi;
}

// ----------------- cluster / DSMEM helpers ---------------------------------
__device__ __forceinline__ unsigned smem_u32(const void* p) {
    unsigned a;
    asm("{ .reg .u64 t; cvta.to.shared.u64 t, %1; cvt.u32.u64 %0, t; }"
        : "=r"(a) : "l"(p));
    return a;
}
__device__ __forceinline__ unsigned mapa_u32(unsigned a, unsigned r) {
    unsigned d;
    asm("mapa.shared::cluster.u32 %0, %1, %2;" : "=r"(d) : "r"(a), "r"(r));
    return d;
}
__device__ __forceinline__ void st_dsmem_v4(unsigned addr, float4 v) {
    asm volatile("st.shared::cluster.v4.f32 [%0], {%1,%2,%3,%4};"
                 :: "r"(addr), "f"(v.x), "f"(v.y), "f"(v.z), "f"(v.w) : "memory");
}
__device__ __forceinline__ void st_dsmem_f(unsigned addr, float v) {
    asm volatile("st.shared::cluster.f32 [%0], %1;" :: "r"(addr), "f"(v) : "memory");
}
__device__ __forceinline__ void cluster_sync_() {
    asm volatile("barrier.cluster.arrive.aligned;" ::: "memory");
    asm volatile("barrier.cluster.wait.aligned;" ::: "memory");
}
__device__ __forceinline__ unsigned cluster_rank_() {
    unsigned r;
    asm("mov.u32 %0, %%cluster_ctarank;" : "=r"(r));
    return r;
}

// ----------------- activations (fp32, ~1e-7 rel) ---------------------------
__device__ __forceinline__ float sigf(float x) {
    return __fdividef(1.0f, 1.0f + __expf(-x));
}
__device__ __forceinline__ float tanhf_(float x) {
    return 1.0f - __fdividef(2.0f, __expf(2.0f * x) + 1.0f);
}

// ============================================================================
// Prep 1: repack recurrent weights into [kpair][j][gate][e], fold L1 biases
// ============================================================================
__global__ void prep_weights(const float* __restrict__ Whh0,
                             const float* __restrict__ Wih1,
                             const float* __restrict__ Whh1,
                             const float* __restrict__ bih1,
                             const float* __restrict__ bhh1)
{
    const int idx = blockIdx.x * blockDim.x + threadIdx.x;
    const int stride = gridDim.x * blockDim.x;
    for (int i = idx; i < 128 * H_ * 8; i += stride) {
        const int e = i & 1, g = (i >> 1) & 3, j = (i >> 3) & (H_ - 1), p = i >> 11;
        const int k = 2 * p + e;
        g_WT0p[i] = Whh0[(g * H_ + j) * H_ + k];
    }
    for (int i = idx; i < 256 * H_ * 8; i += stride) {
        const int e = i & 1, g = (i >> 1) & 3, j = (i >> 3) & (H_ - 1), p = i >> 11;
        const int k = 2 * p + e;
        const int n = g * H_ + j;
        g_WT1p[i] = (k < H_) ? Wih1[n * H_ + k] : Whh1[n * H_ + (k - H_)];
    }
    for (int i = idx; i < G4; i += stride) {
        const int g = i & 3, j = i >> 2;
        g_b1[i] = bih1[g * H_ + j] + bhh1[g * H_ + j];
    }
}

// ============================================================================
// Prep 2: layernorm(state) then gx0 = xn @ W_ih0^T + (b_ih0 + b_hh0)
// ============================================================================
__global__ void prep_gx0(const float* __restrict__ state,
                         const float* __restrict__ gamma,
                         const float* __restrict__ beta,
                         const float* __restrict__ Wih0,
                         const float* __restrict__ bih0,
                         const float* __restrict__ bhh0)
{
    const int b = blockIdx.x;
    const int t = threadIdx.x;
    __shared__ float xs[D_];
    __shared__ float xn[D_];

    if (t < D_) xs[t] = state[b * D_ + t];
    __syncthreads();

    float mu = 0.f;
    #pragma unroll
    for (int k = 0; k < D_; k++) mu += xs[k];
    mu *= (1.0f / D_);
    float var = 0.f;
    #pragma unroll
    for (int k = 0; k < D_; k++) { const float d = xs[k] - mu; var += d * d; }
    var *= (1.0f / D_);
    const float rs = rsqrtf(var + 1e-5f);

    if (t < D_) xn[t] = (xs[t] - mu) * rs * gamma[t] + beta[t];
    __syncthreads();

    #pragma unroll
    for (int g = 0; g < 4; g++) {
        const int n = g * H_ + t;
        const float* w = Wih0 + n * D_;
        float acc = bih0[n] + bhh0[n];
        #pragma unroll
        for (int k = 0; k < D_; k++) acc += xn[k] * w[k];
        g_gx0[(b * H_ + t) * 4 + g] = acc;
    }
}

// ============================================================================
// dynamic smem layout (floats)
// ============================================================================
#define OFF_H0   0                         // [MBT][HS]
#define OFF_H1   (OFF_H0 + MBT * HS)       // [MBT][HS]
#define OFF_R0   (OFF_H1 + MBT * HS)       // [MBT][128][4]   peer L0 partials
#define OFF_R1   (OFF_R0 + MBT * 128 * 4)  // [MBT][128][4]   peer L1 partials
#define OFF_GX   (OFF_R1 + MBT * 128 * 4)  // [MBT][128][4]   gx0 (duty units)
#define OFF_B1   (OFF_GX + MBT * 128 * 4)  // [128][4]
#define OFF_FC   (OFF_B1 + 128 * 4)        // [8][132]
#define OFF_FCB  (OFF_FC + 8 * 132)        // [8]
#define OFF_FCO  (OFF_FCB + 8)             // [MBT][8]  own fc partial (rank1)
#define OFF_FCR  (OFF_FCO + MBT * 8)       // [MBT][8]  recv fc partial
#define SMEM_FLOATS (OFF_FCR + MBT * 8)
#define SMEM_BYTES  (SMEM_FLOATS * 4)

// 32 iterations x 2 k-pairs over 64 pairs (one K-half of one matrix block)
__device__ __forceinline__ void gemm_half(const float* __restrict__ wbase,
                                          const float* __restrict__ h,
                                          u64 (&acc)[MBT][4])
{
    #pragma unroll 2
    for (int i = 0; i < 32; i++) {
        const float* wp = wbase + i * 4096;
        const ulonglong2 wA0 = *(const ulonglong2*)(wp);         // pair 2i, gates 0,1
        const ulonglong2 wB0 = *(const ulonglong2*)(wp + 4);     // pair 2i, gates 2,3
        const ulonglong2 wA1 = *(const ulonglong2*)(wp + 2048);  // pair 2i+1
        const ulonglong2 wB1 = *(const ulonglong2*)(wp + 2052);
        #pragma unroll
        for (int r = 0; r < MBT; r++) {
            const float4 h4 = *(const float4*)(h + r * HS + i * 4);
            const u64 ha = *(const u64*)&h4.x;
            const u64 hb = *(const u64*)&h4.z;
            acc[r][0] = ffma2(ha, wA0.x, acc[r][0]);
            acc[r][1] = ffma2(ha, wA0.y, acc[r][1]);
            acc[r][2] = ffma2(ha, wB0.x, acc[r][2]);
            acc[r][3] = ffma2(ha, wB0.y, acc[r][3]);
            acc[r][0] = ffma2(hb, wA1.x, acc[r][0]);
            acc[r][1] = ffma2(hb, wA1.y, acc[r][1]);
            acc[r][2] = ffma2(hb, wB1.x, acc[r][2]);
            acc[r][3] = ffma2(hb, wB1.y, acc[r][3]);
        }
    }
}

// ============================================================================
// Main: 74 clusters x 2 CTAs x 256 threads. Cluster owns 14 batch rows.
// CTA rank r: GEMM K-half = units [128r,128r+128); cell duty = same units.
// Only inter-CTA data: partial gate sums, via DSMEM + 2 cluster syncs/step.
// ============================================================================
__global__ void __launch_bounds__(256, 1) __cluster_dims__(2, 1, 1)
lstm_main(const float* __restrict__ fcW,
          const float* __restrict__ fcb,
          float* __restrict__ out)
{
    extern __shared__ float sm[];
    float* sh0  = sm + OFF_H0;
    float* sh1  = sm + OFF_H1;
    float* sr0  = sm + OFF_R0;
    float* sr1  = sm + OFF_R1;
    float* sgx  = sm + OFF_GX;
    float* sb1  = sm + OFF_B1;
    float* sfc  = sm + OFF_FC;
    float* sfcb = sm + OFF_FCB;
    float* sfco = sm + OFF_FCO;
    float* sfcr = sm + OFF_FCR;

    const int t = threadIdx.x;
    const unsigned rank = cluster_rank_();
    const unsigned peer = rank ^ 1u;
    const int cid = blockIdx.x >> 1;
    const int b0  = (cid * B_) / NCL;
    const int cnt = (((cid + 1) * B_) / NCL) - b0;
    const int duty = rank * 128;
    const bool is_cons = ((t >> 7) == (int)rank);
    const int u = t & 127;

    // ---------------- stage constants into SMEM ----------------------------
    for (int i = t; i < MBT * 128; i += 256) {
        const int r = i >> 7, uu = i & 127;
        const int brow = b0 + (r < cnt ? r : cnt - 1);
        *(float4*)(sgx + i * 4) =
            *(const float4*)(g_gx0 + (brow * H_ + duty + uu) * 4);
    }
    for (int i = t; i < 128; i += 256)
        *(float4*)(sb1 + i * 4) = *(const float4*)(g_b1 + (duty + i) * 4);
    for (int i = t; i < 8 * 128; i += 256) {
        const int a = i >> 7, uu = i & 127;
        sfc[a * 132 + uu] = fcW[a * H_ + duty + uu];
    }
    if (t < 8) sfcb[t] = fcb[t];
    for (int i = t; i < MBT * HS; i += 256) { sh0[i] = 0.f; sh1[i] = 0.f; }

    // DSMEM target addresses in peer CTA
    const unsigned p_r0 = mapa_u32(smem_u32(sr0), peer);
    const unsigned p_r1 = mapa_u32(smem_u32(sr1), peer);
    const unsigned p_fcr = mapa_u32(smem_u32(sfcr), peer);

    float c0[MBT], c1[MBT];
    #pragma unroll
    for (int r = 0; r < MBT; r++) { c0[r] = 0.f; c1[r] = 0.f; }

    const float4 b1v = *(const float4*)(sb1 + u * 4);

    const float* w0base  = g_WT0p + (rank * 64) * 2048 + t * 8;
    const float* w1abase = g_WT1p + (rank * 64) * 2048 + t * 8;
    const float* w1bbase = g_WT1p + (128 + rank * 64) * 2048 + t * 8;

    __syncthreads();
    cluster_sync_();

    for (int step = 0; step < T_; step++) {
        // ================= layer 0: partial GEMM over own K-half ===========
        u64 acc[MBT][4];
        #pragma unroll
        for (int r = 0; r < MBT; r++)
            { acc[r][0] = 0; acc[r][1] = 0; acc[r][2] = 0; acc[r][3] = 0; }
        gemm_half(w0base, sh0, acc);

        if (!is_cons) {   // send partials for peer's duty units
            #pragma unroll
            for (int r = 0; r < MBT; r++) {
                float4 v = make_float4(hadd2(acc[r][0]), hadd2(acc[r][1]),
                                       hadd2(acc[r][2]), hadd2(acc[r][3]));
                st_dsmem_v4(p_r0 + (unsigned)((r * 128 + u) * 16), v);
            }
        }
        cluster_sync_();   // sync#1: L0 partials visible (+ fc partial of step-1)

        // FC output of previous step (rank1 combines)
        if (rank == 1 && step > 0 && t < MBT * 8) {
            const int row = t >> 3, a = t & 7;
            if (row < cnt)
                out[((b0 + row) * T_ + (step - 1)) * A_ + a] =
                    tanhf_(sfco[t] + sfcr[t] + sfcb[a]);
        }

        if (is_cons) {     // cell 0 for duty units
            #pragma unroll
            for (int r = 0; r < MBT; r++) {
                const float4 pv = *(const float4*)(sr0 + (r * 128 + u) * 4);
                const float4 gx = *(const float4*)(sgx + (r * 128 + u) * 4);
                const float gi = hadd2(acc[r][0]) + pv.x + gx.x;
                const float gf = hadd2(acc[r][1]) + pv.y + gx.y;
                const float gg = hadd2(acc[r][2]) + pv.z + gx.z;
                const float go = hadd2(acc[r][3]) + pv.w + gx.w;
                const float cn = sigf(gf) * c0[r] + sigf(gi) * tanhf_(gg);
                c0[r] = cn;
                sh0[r * HS + u] = sigf(go) * tanhf_(cn);
            }
        }
        __syncthreads();   // h0_new ready

        // ================= layer 1: partial GEMM over own K-half ===========
        #pragma unroll
        for (int r = 0; r < MBT; r++)
            { acc[r][0] = 0; acc[r][1] = 0; acc[r][2] = 0; acc[r][3] = 0; }
        gemm_half(w1abase, sh0, acc);   // h0_new half
        gemm_half(w1bbase, sh1, acc);   // h1_old half

        if (!is_cons) {
            #pragma unroll
            for (int r = 0; r < MBT; r++) {
                float4 v = make_float4(hadd2(acc[r][0]), hadd2(acc[r][1]),
                                       hadd2(acc[r][2]), hadd2(acc[r][3]));
                st_dsmem_v4(p_r1 + (unsigned)((r * 128 + u) * 16), v);
            }
        }
        cluster_sync_();   // sync#2: L1 partials visible

        if (is_cons) {     // cell 1 for duty units
            #pragma unroll
            for (int r = 0; r < MBT; r++) {
                const float4 pv = *(const float4*)(sr1 + (r * 128 + u) * 4);
                const float gi = hadd2(acc[r][0]) + pv.x + b1v.x;
                const float gf = hadd2(acc[r][1]) + pv.y + b1v.y;
                const float gg = hadd2(acc[r][2]) + pv.z + b1v.z;
                const float go = hadd2(acc[r][3]) + pv.w + b1v.w;
                const float cn = sigf(gf) * c1[r] + sigf(gi) * tanhf_(gg);
                c1[r] = cn;
                sh1[r * HS + u] = sigf(go) * tanhf_(cn);
            }
        }
        __syncthreads();   // h1_new ready

        // ============ FC partial over own 128 units of h1 ==================
        if (t < MBT * 8) {
            const int row = t >> 3, a = t & 7;
            float f = 0.f;
            #pragma unroll 8
            for (int uu = 0; uu < 128; uu++)
                f += sh1[row * HS + uu] * sfc[a * 132 + uu];
            if (rank == 0) st_dsmem_f(p_fcr + (unsigned)(t * 4), f);
            else           sfco[t] = f;
        }
        // fc partial lands before sync#1 of next step
    }

    cluster_sync_();       // last fc partial visible
    if (rank == 1 && t < MBT * 8) {
        const int row = t >> 3, a = t & 7;
        if (row < cnt)
            out[((b0 + row) * T_ + (T_ - 1)) * A_ + a] =
                tanhf_(sfco[t] + sfcr[t] + sfcb[a]);
    }
}

// ============================================================================
extern "C" void kernel_launch(void* const* d_in, const int* in_sizes, int n_in,
                              void* d_out, int out_size)
{
    const float* state = (const float*)d_in[0];
    const float* gamma = (const float*)d_in[1];
    const float* beta  = (const float*)d_in[2];
    const float* Wih0  = (const float*)d_in[3];
    const float* Whh0  = (const float*)d_in[4];
    const float* bih0  = (const float*)d_in[5];
    const float* bhh0  = (const float*)d_in[6];
    const float* Wih1  = (const float*)d_in[7];
    const float* Whh1  = (const float*)d_in[8];
    const float* bih1  = (const float*)d_in[9];
    const float* bhh1  = (const float*)d_in[10];
    const float* fcW   = (const float*)d_in[11];
    const float* fcb   = (const float*)d_in[12];
    float* out = (float*)d_out;

    static bool attr_set = false;
    if (!attr_set) {
        cudaFuncSetAttribute(lstm_main,
                             cudaFuncAttributeMaxDynamicSharedMemorySize,
                             SMEM_BYTES);
        attr_set = true;
    }

    prep_weights<<<264, 256>>>(Whh0, Wih1, Whh1, bih1, bhh1);
    prep_gx0<<<B_, 256>>>(state, gamma, beta, Wih0, bih0, bhh0);
    lstm_main<<<GRID, 256, SMEM_BYTES>>>(fcW, fcb, out);
}

// round 9
// speedup vs baseline: 1.0925x; 1.0247x over previous
#include <cuda_runtime.h>

#define B_    1024
#define D_    64
#define H_    256
#define G4    1024       // 4*H
#define T_    128
#define A_    8
#define NCL   74         // clusters
#define GRID  148        // 74 clusters * 2 CTAs
#define MBT   14         // batch rows per cluster (padded; real 13 or 14)
#define RS_   256        // floats per row in h buffers
#define HBUF  (MBT * RS_)

// ----------------- static device scratch (no allocations allowed) ----------
// packed weights: [kpair][j][gate][e], e = k parity (8 floats per (kpair,j))
__device__ float g_WT0p[128 * H_ * 8];        // W_hh0^T packed   (1 MB)
__device__ float g_WT1p[256 * H_ * 8];        // [W_ih1;W_hh1]^T packed (2 MB)
__device__ float g_b1[G4];                    // (b_ih1+b_hh1) as [j][gate]
__device__ float g_gx0[B_ * G4];              // xn@W_ih0^T + b0, as [b][j][gate]

typedef unsigned long long u64;

// ----------------- packed f32x2 helpers (sm_103a FFMA2) --------------------
__device__ __forceinline__ u64 ffma2(u64 a, u64 b, u64 c) {
    u64 d;
    asm("fma.rn.f32x2 %0, %1, %2, %3;" : "=l"(d) : "l"(a), "l"(b), "l"(c));
    return d;
}
__device__ __forceinline__ float hadd2(u64 v) {
    float lo, hi;
    asm("mov.b64 {%0, %1}, %2;" : "=f"(lo), "=f"(hi) : "l"(v));
    return lo + hi;
}

// ----------------- cluster / DSMEM helpers ---------------------------------
__device__ __forceinline__ unsigned smem_u32(const void* p) {
    unsigned a;
    asm("{ .reg .u64 t; cvta.to.shared.u64 t, %1; cvt.u32.u64 %0, t; }"
        : "=r"(a) : "l"(p));
    return a;
}
__device__ __forceinline__ unsigned mapa_u32(unsigned a, unsigned r) {
    unsigned d;
    asm("mapa.shared::cluster.u32 %0, %1, %2;" : "=r"(d) : "r"(a), "r"(r));
    return d;
}
__device__ __forceinline__ void st_dsmem_f(unsigned addr, float v) {
    asm volatile("st.shared::cluster.f32 [%0], %1;" :: "r"(addr), "f"(v) : "memory");
}
__device__ __forceinline__ void cluster_sync_() {
    asm volatile("barrier.cluster.arrive.aligned;" ::: "memory");
    asm volatile("barrier.cluster.wait.aligned;" ::: "memory");
}
__device__ __forceinline__ unsigned cluster_rank_() {
    unsigned r;
    asm("mov.u32 %0, %%cluster_ctarank;" : "=r"(r));
    return r;
}

// ----------------- activations (fp32, ~1e-7 rel) ---------------------------
__device__ __forceinline__ float sigf(float x) {
    return __fdividef(1.0f, 1.0f + __expf(-x));
}
__device__ __forceinline__ float tanhf_(float x) {
    return 1.0f - __fdividef(2.0f, __expf(2.0f * x) + 1.0f);
}

// ============================================================================
// Prep 1: repack recurrent weights into [kpair][j][gate][e], fold L1 biases
// ============================================================================
__global__ void prep_weights(const float* __restrict__ Whh0,
                             const float* __restrict__ Wih1,
                             const float* __restrict__ Whh1,
                             const float* __restrict__ bih1,
                             const float* __restrict__ bhh1)
{
    const int idx = blockIdx.x * blockDim.x + threadIdx.x;
    const int stride = gridDim.x * blockDim.x;
    for (int i = idx; i < 128 * H_ * 8; i += stride) {
        const int e = i & 1, g = (i >> 1) & 3, j = (i >> 3) & (H_ - 1), p = i >> 11;
        const int k = 2 * p + e;
        g_WT0p[i] = Whh0[(g * H_ + j) * H_ + k];
    }
    for (int i = idx; i < 256 * H_ * 8; i += stride) {
        const int e = i & 1, g = (i >> 1) & 3, j = (i >> 3) & (H_ - 1), p = i >> 11;
        const int k = 2 * p + e;
        const int n = g * H_ + j;
        g_WT1p[i] = (k < H_) ? Wih1[n * H_ + k] : Whh1[n * H_ + (k - H_)];
    }
    for (int i = idx; i < G4; i += stride) {
        const int g = i & 3, j = i >> 2;
        g_b1[i] = bih1[g * H_ + j] + bhh1[g * H_ + j];
    }
}

// ============================================================================
// Prep 2: layernorm(state) then gx0 = xn @ W_ih0^T + (b_ih0 + b_hh0)
// ============================================================================
__global__ void prep_gx0(const float* __restrict__ state,
                         const float* __restrict__ gamma,
                         const float* __restrict__ beta,
                         const float* __restrict__ Wih0,
                         const float* __restrict__ bih0,
                         const float* __restrict__ bhh0)
{
    const int b = blockIdx.x;
    const int t = threadIdx.x;
    __shared__ float xs[D_];
    __shared__ float xn[D_];

    if (t < D_) xs[t] = state[b * D_ + t];
    __syncthreads();

    float mu = 0.f;
    #pragma unroll
    for (int k = 0; k < D_; k++) mu += xs[k];
    mu *= (1.0f / D_);
    float var = 0.f;
    #pragma unroll
    for (int k = 0; k < D_; k++) { const float d = xs[k] - mu; var += d * d; }
    var *= (1.0f / D_);
    const float rs = rsqrtf(var + 1e-5f);

    if (t < D_) xn[t] = (xs[t] - mu) * rs * gamma[t] + beta[t];
    __syncthreads();

    #pragma unroll
    for (int g = 0; g < 4; g++) {
        const int n = g * H_ + t;
        const float* w = Wih0 + n * D_;
        float acc = bih0[n] + bhh0[n];
        #pragma unroll
        for (int k = 0; k < D_; k++) acc += xn[k] * w[k];
        g_gx0[(b * H_ + t) * 4 + g] = acc;
    }
}

// ============================================================================
// dynamic smem layout (floats)
// ============================================================================
#define OFF_H0   0                          // [2][MBT][RS_]  h0, parity bufs
#define OFF_H1   (OFF_H0 + 2 * HBUF)        // [2][MBT][RS_]  h1
#define OFF_SP   (OFF_H1 + 2 * HBUF)        // [MBT][128][4]  K-half partials
#define OFF_GX   (OFF_SP + MBT * 128 * 4)   // [MBT][128][4]  gx0 (duty units)
#define OFF_B1   (OFF_GX + MBT * 128 * 4)   // [128][4]       b1  (duty units)
#define OFF_FC   (OFF_B1 + 128 * 4)         // [8][256]       full fcW
#define OFF_FCB  (OFF_FC + 8 * 256)         // [8]
#define SMEM_FLOATS (OFF_FCB + 8)
#define SMEM_BYTES  (SMEM_FLOATS * 4)

// N-split GEMM: 64 kpairs (one K-half) x 128 duty columns x 4 gates.
// wbase = packed weights at (kpair_base, j=duty+jj); h = row base (+K-half off).
__device__ __forceinline__ void gemm_ns(const float* __restrict__ wbase,
                                        const float* __restrict__ h,
                                        u64 (&acc)[MBT][4])
{
    #pragma unroll 2
    for (int i = 0; i < 32; i++) {
        const float* wp = wbase + i * 4096;                  // kpair 2i
        const ulonglong2 wA0 = *(const ulonglong2*)(wp);     // gates 0,1
        const ulonglong2 wB0 = *(const ulonglong2*)(wp + 4); // gates 2,3
        const ulonglong2 wA1 = *(const ulonglong2*)(wp + 2048);  // kpair 2i+1
        const ulonglong2 wB1 = *(const ulonglong2*)(wp + 2052);
        #pragma unroll
        for (int r = 0; r < MBT; r++) {
            const float4 h4 = *(const float4*)(h + r * RS_ + i * 4);
            const u64 ha = *(const u64*)&h4.x;
            const u64 hb = *(const u64*)&h4.z;
            acc[r][0] = ffma2(ha, wA0.x, acc[r][0]);
            acc[r][1] = ffma2(ha, wA0.y, acc[r][1]);
            acc[r][2] = ffma2(ha, wB0.x, acc[r][2]);
            acc[r][3] = ffma2(ha, wB0.y, acc[r][3]);
            acc[r][0] = ffma2(hb, wA1.x, acc[r][0]);
            acc[r][1] = ffma2(hb, wA1.y, acc[r][1]);
            acc[r][2] = ffma2(hb, wB1.x, acc[r][2]);
            acc[r][3] = ffma2(hb, wB1.y, acc[r][3]);
        }
    }
}

// ============================================================================
// Main: 74 clusters x 2 CTAs x 256 threads. Cluster owns 14 batch rows.
// CTA rank computes ALL K for its 128 duty gate-columns (N-split). K is split
// 2-way inside the CTA (kh = t>>7); partials combined via CTA-local SMEM.
// h is broadcast to the peer via DSMEM into parity double-buffers: writer
// targets buf pb^1 while readers use pb -> no WAR hazards by construction.
// ============================================================================
__global__ void __launch_bounds__(256, 1) __cluster_dims__(2, 1, 1)
lstm_main(const float* __restrict__ fcW,
          const float* __restrict__ fcb,
          float* __restrict__ out)
{
    extern __shared__ float sm[];
    float* sh0  = sm + OFF_H0;
    float* sh1  = sm + OFF_H1;
    float* sp   = sm + OFF_SP;
    float* sgx  = sm + OFF_GX;
    float* sb1  = sm + OFF_B1;
    float* sfc  = sm + OFF_FC;
    float* sfcb = sm + OFF_FCB;

    const int t = threadIdx.x;
    const unsigned rank = cluster_rank_();
    const unsigned peer = rank ^ 1u;
    const int cid  = blockIdx.x >> 1;
    const int b0   = (cid * B_) / NCL;
    const int cnt  = (((cid + 1) * B_) / NCL) - b0;
    const int duty = (int)rank * 128;
    const int jj   = t & 127;
    const int kh   = t >> 7;

    // ---------------- stage constants into SMEM ----------------------------
    for (int i = t; i < MBT * 128; i += 256) {
        const int r = i >> 7, u = i & 127;
        const int brow = b0 + (r < cnt ? r : cnt - 1);
        *(float4*)(sgx + i * 4) =
            *(const float4*)(g_gx0 + (brow * H_ + duty + u) * 4);
    }
    for (int i = t; i < 128; i += 256)
        *(float4*)(sb1 + i * 4) = *(const float4*)(g_b1 + (duty + i) * 4);
    for (int i = t; i < A_ * H_; i += 256) sfc[i] = fcW[i];
    if (t < A_) sfcb[t] = fcb[t];
    for (int i = t; i < HBUF; i += 256) { sh0[i] = 0.f; sh1[i] = 0.f; }  // buf 0

    const unsigned p_h0 = mapa_u32(smem_u32(sh0), peer);
    const unsigned p_h1 = mapa_u32(smem_u32(sh1), peer);

    float c0[MBT], c1[MBT];
    #pragma unroll
    for (int r = 0; r < MBT; r++) { c0[r] = 0.f; c1[r] = 0.f; }

    const float* w0base  = g_WT0p + (kh * 64) * 2048 + (duty + jj) * 8;
    const float* w1abase = g_WT1p + (kh * 64) * 2048 + (duty + jj) * 8;
    const float* w1bbase = g_WT1p + (128 + kh * 64) * 2048 + (duty + jj) * 8;
    const int hoff = kh * 128;

    __syncthreads();
    cluster_sync_();     // staging done in both CTAs (incl. peer SMEM ready)

    const float4 b1v = *(const float4*)(sb1 + jj * 4);

    int pb = 0;
    for (int step = 0; step < T_; step++) {
        // ================= layer 0: full-K GEMM on duty columns ============
        u64 acc[MBT][4];
        #pragma unroll
        for (int r = 0; r < MBT; r++)
            { acc[r][0] = 0; acc[r][1] = 0; acc[r][2] = 0; acc[r][3] = 0; }
        gemm_ns(w0base, sh0 + pb * HBUF + hoff, acc);

        if (kh) {           // upper K-half: publish partials
            #pragma unroll
            for (int r = 0; r < MBT; r++)
                *(float4*)(sp + (r * 128 + jj) * 4) =
                    make_float4(hadd2(acc[r][0]), hadd2(acc[r][1]),
                                hadd2(acc[r][2]), hadd2(acc[r][3]));
        }
        __syncthreads();
        if (!kh) {          // lower K-half: combine + cell0 + broadcast h0
            #pragma unroll
            for (int r = 0; r < MBT; r++) {
                const float4 pv = *(const float4*)(sp + (r * 128 + jj) * 4);
                const float4 gx = *(const float4*)(sgx + (r * 128 + jj) * 4);
                const float gi = hadd2(acc[r][0]) + pv.x + gx.x;
                const float gf = hadd2(acc[r][1]) + pv.y + gx.y;
                const float gg = hadd2(acc[r][2]) + pv.z + gx.z;
                const float go = hadd2(acc[r][3]) + pv.w + gx.w;
                const float cn = sigf(gf) * c0[r] + sigf(gi) * tanhf_(gg);
                c0[r] = cn;
                const float hv = sigf(go) * tanhf_(cn);
                const int off = (pb ^ 1) * HBUF + r * RS_ + duty + jj;
                sh0[off] = hv;
                st_dsmem_f(p_h0 + (unsigned)off * 4u, hv);
            }
        }
        cluster_sync_();    // h0_new (both halves) visible everywhere

        // ================= layer 1 =========================================
        #pragma unroll
        for (int r = 0; r < MBT; r++)
            { acc[r][0] = 0; acc[r][1] = 0; acc[r][2] = 0; acc[r][3] = 0; }
        gemm_ns(w1abase, sh0 + (pb ^ 1) * HBUF + hoff, acc);  // h0_new
        gemm_ns(w1bbase, sh1 + pb * HBUF + hoff, acc);        // h1_old

        if (kh) {
            #pragma unroll
            for (int r = 0; r < MBT; r++)
                *(float4*)(sp + (r * 128 + jj) * 4) =
                    make_float4(hadd2(acc[r][0]), hadd2(acc[r][1]),
                                hadd2(acc[r][2]), hadd2(acc[r][3]));
        }
        __syncthreads();
        if (!kh) {
            #pragma unroll
            for (int r = 0; r < MBT; r++) {
                const float4 pv = *(const float4*)(sp + (r * 128 + jj) * 4);
                const float gi = hadd2(acc[r][0]) + pv.x + b1v.x;
                const float gf = hadd2(acc[r][1]) + pv.y + b1v.y;
                const float gg = hadd2(acc[r][2]) + pv.z + b1v.z;
                const float go = hadd2(acc[r][3]) + pv.w + b1v.w;
                const float cn = sigf(gf) * c1[r] + sigf(gi) * tanhf_(gg);
                c1[r] = cn;
                const float hv = sigf(go) * tanhf_(cn);
                const int off = (pb ^ 1) * HBUF + r * RS_ + duty + jj;
                sh1[off] = hv;
                st_dsmem_f(p_h1 + (unsigned)off * 4u, hv);
            }
        }
        cluster_sync_();    // h1_new visible everywhere

        // ============ FC head: each rank outputs its 7 rows directly =======
        if (t < 56) {
            const int row = (int)rank * 7 + (t >> 3);   // cluster row 0..13
            const int a = t & 7;
            if (row < cnt) {
                const float* hrow = sh1 + (pb ^ 1) * HBUF + row * RS_;
                const float* wrow = sfc + a * H_;
                float f = 0.f;
                #pragma unroll 8
                for (int u = 0; u < H_; u++) f += hrow[u] * wrow[u];
                out[((b0 + row) * T_ + step) * A_ + a] = tanhf_(f + sfcb[a]);
            }
        }
        pb ^= 1;
    }
}

// ============================================================================
extern "C" void kernel_launch(void* const* d_in, const int* in_sizes, int n_in,
                              void* d_out, int out_size)
{
    const float* state = (const float*)d_in[0];
    const float* gamma = (const float*)d_in[1];
    const float* beta  = (const float*)d_in[2];
    const float* Wih0  = (const float*)d_in[3];
    const float* Whh0  = (const float*)d_in[4];
    const float* bih0  = (const float*)d_in[5];
    const float* bhh0  = (const float*)d_in[6];
    const float* Wih1  = (const float*)d_in[7];
    const float* Whh1  = (const float*)d_in[8];
    const float* bih1  = (const float*)d_in[9];
    const float* bhh1  = (const float*)d_in[10];
    const float* fcW   = (const float*)d_in[11];
    const float* fcb   = (const float*)d_in[12];
    float* out = (float*)d_out;

    // Host-side config, capture-safe, no static guards (rules: deterministic).
    cudaFuncSetAttribute(lstm_main,
                         cudaFuncAttributeMaxDynamicSharedMemorySize,
                         SMEM_BYTES);

    prep_weights<<<264, 256>>>(Whh0, Wih1, Whh1, bih1, bhh1);
    prep_gx0<<<B_, 256>>>(state, gamma, beta, Wih0, bih0, bhh0);
    lstm_main<<<GRID, 256, SMEM_BYTES>>>(fcW, fcb, out);
}

// round 10
// speedup vs baseline: 1.0942x; 1.0016x over previous
#include <cuda_runtime.h>

#define B_    1024
#define D_    64
#define H_    256
#define G4    1024       // 4*H
#define T_    128
#define A_    8
#define NCL   74         // clusters
#define GRID  148        // 74 clusters * 2 CTAs
#define MBT   14         // batch rows per cluster (padded; real 13 or 14)
#define RS_   256        // floats per row in h buffers
#define HBUF  (MBT * RS_)

// ----------------- static device scratch (no allocations allowed) ----------
// packed weights: [kpair][j][gate][e], e = k parity (8 floats per (kpair,j))
__device__ float g_WT0p[128 * H_ * 8];        // W_hh0^T packed   (1 MB)
__device__ float g_WT1p[256 * H_ * 8];        // [W_ih1;W_hh1]^T packed (2 MB)
__device__ float g_b1[G4];                    // (b_ih1+b_hh1) as [j][gate]
__device__ float g_gx0[B_ * G4];              // xn@W_ih0^T + b0, as [b][j][gate]

typedef unsigned long long u64;

// ----------------- packed f32x2 helpers (sm_103a FFMA2) --------------------
__device__ __forceinline__ u64 ffma2(u64 a, u64 b, u64 c) {
    u64 d;
    asm("fma.rn.f32x2 %0, %1, %2, %3;" : "=l"(d) : "l"(a), "l"(b), "l"(c));
    return d;
}
__device__ __forceinline__ float hadd2(u64 v) {
    float lo, hi;
    asm("mov.b64 {%0, %1}, %2;" : "=f"(lo), "=f"(hi) : "l"(v));
    return lo + hi;
}

// ----------------- cluster / DSMEM helpers ---------------------------------
__device__ __forceinline__ unsigned smem_u32(const void* p) {
    unsigned a;
    asm("{ .reg .u64 t; cvta.to.shared.u64 t, %1; cvt.u32.u64 %0, t; }"
        : "=r"(a) : "l"(p));
    return a;
}
__device__ __forceinline__ unsigned mapa_u32(unsigned a, unsigned r) {
    unsigned d;
    asm("mapa.shared::cluster.u32 %0, %1, %2;" : "=r"(d) : "r"(a), "r"(r));
    return d;
}
__device__ __forceinline__ void st_dsmem_f(unsigned addr, float v) {
    asm volatile("st.shared::cluster.f32 [%0], %1;" :: "r"(addr), "f"(v) : "memory");
}
__device__ __forceinline__ void cluster_sync_() {
    asm volatile("barrier.cluster.arrive.aligned;" ::: "memory");
    asm volatile("barrier.cluster.wait.aligned;" ::: "memory");
}
__device__ __forceinline__ unsigned cluster_rank_() {
    unsigned r;
    asm("mov.u32 %0, %%cluster_ctarank;" : "=r"(r));
    return r;
}

// ----------------- activations (fp32, ~1e-7 rel) ---------------------------
__device__ __forceinline__ float sigf(float x) {
    return __fdividef(1.0f, 1.0f + __expf(-x));
}
__device__ __forceinline__ float tanhf_(float x) {
    return 1.0f - __fdividef(2.0f, __expf(2.0f * x) + 1.0f);
}

// ============================================================================
// Prep 1: repack recurrent weights into [kpair][j][gate][e], fold L1 biases
// ============================================================================
__global__ void prep_weights(const float* __restrict__ Whh0,
                             const float* __restrict__ Wih1,
                             const float* __restrict__ Whh1,
                             const float* __restrict__ bih1,
                             const float* __restrict__ bhh1)
{
    const int idx = blockIdx.x * blockDim.x + threadIdx.x;
    const int stride = gridDim.x * blockDim.x;
    for (int i = idx; i < 128 * H_ * 8; i += stride) {
        const int e = i & 1, g = (i >> 1) & 3, j = (i >> 3) & (H_ - 1), p = i >> 11;
        const int k = 2 * p + e;
        g_WT0p[i] = Whh0[(g * H_ + j) * H_ + k];
    }
    for (int i = idx; i < 256 * H_ * 8; i += stride) {
        const int e = i & 1, g = (i >> 1) & 3, j = (i >> 3) & (H_ - 1), p = i >> 11;
        const int k = 2 * p + e;
        const int n = g * H_ + j;
        g_WT1p[i] = (k < H_) ? Wih1[n * H_ + k] : Whh1[n * H_ + (k - H_)];
    }
    for (int i = idx; i < G4; i += stride) {
        const int g = i & 3, j = i >> 2;
        g_b1[i] = bih1[g * H_ + j] + bhh1[g * H_ + j];
    }
}

// ============================================================================
// Prep 2: layernorm(state) then gx0 = xn @ W_ih0^T + (b_ih0 + b_hh0)
// ============================================================================
__global__ void prep_gx0(const float* __restrict__ state,
                         const float* __restrict__ gamma,
                         const float* __restrict__ beta,
                         const float* __restrict__ Wih0,
                         const float* __restrict__ bih0,
                         const float* __restrict__ bhh0)
{
    const int b = blockIdx.x;
    const int t = threadIdx.x;
    __shared__ float xs[D_];
    __shared__ float xn[D_];

    if (t < D_) xs[t] = state[b * D_ + t];
    __syncthreads();

    float mu = 0.f;
    #pragma unroll
    for (int k = 0; k < D_; k++) mu += xs[k];
    mu *= (1.0f / D_);
    float var = 0.f;
    #pragma unroll
    for (int k = 0; k < D_; k++) { const float d = xs[k] - mu; var += d * d; }
    var *= (1.0f / D_);
    const float rs = rsqrtf(var + 1e-5f);

    if (t < D_) xn[t] = (xs[t] - mu) * rs * gamma[t] + beta[t];
    __syncthreads();

    #pragma unroll
    for (int g = 0; g < 4; g++) {
        const int n = g * H_ + t;
        const float* w = Wih0 + n * D_;
        float acc = bih0[n] + bhh0[n];
        #pragma unroll
        for (int k = 0; k < D_; k++) acc += xn[k] * w[k];
        g_gx0[(b * H_ + t) * 4 + g] = acc;
    }
}

// ============================================================================
// dynamic smem layout (floats)
// ============================================================================
#define OFF_H0   0                          // [2][MBT][RS_]  h0, parity bufs
#define OFF_H1   (OFF_H0 + 2 * HBUF)        // [2][MBT][RS_]  h1
#define OFF_SP   (OFF_H1 + 2 * HBUF)        // [MBT][128][4]  K-half partials
#define OFF_GX   (OFF_SP + MBT * 128 * 4)   // [MBT][128][4]  gx0 (duty units)
#define OFF_B1   (OFF_GX + MBT * 128 * 4)   // [128][4]       b1  (duty units)
#define OFF_FC   (OFF_B1 + 128 * 4)         // [8][256]       full fcW
#define OFF_FCB  (OFF_FC + 8 * 256)         // [8]
#define SMEM_FLOATS (OFF_FCB + 8)
#define SMEM_BYTES  (SMEM_FLOATS * 4)

// N-split GEMM: 64 kpairs (one K-half) x 128 duty columns x 4 gates.
// wbase = packed weights at (kpair_base, j=duty+jj); h = row base (+K-half off).
__device__ __forceinline__ void gemm_ns(const float* __restrict__ wbase,
                                        const float* __restrict__ h,
                                        u64 (&acc)[MBT][4])
{
    #pragma unroll 2
    for (int i = 0; i < 32; i++) {
        const float* wp = wbase + i * 4096;                  // kpair 2i
        const ulonglong2 wA0 = *(const ulonglong2*)(wp);     // gates 0,1
        const ulonglong2 wB0 = *(const ulonglong2*)(wp + 4); // gates 2,3
        const ulonglong2 wA1 = *(const ulonglong2*)(wp + 2048);  // kpair 2i+1
        const ulonglong2 wB1 = *(const ulonglong2*)(wp + 2052);
        #pragma unroll
        for (int r = 0; r < MBT; r++) {
            const float4 h4 = *(const float4*)(h + r * RS_ + i * 4);
            const u64 ha = *(const u64*)&h4.x;
            const u64 hb = *(const u64*)&h4.z;
            acc[r][0] = ffma2(ha, wA0.x, acc[r][0]);
            acc[r][1] = ffma2(ha, wA0.y, acc[r][1]);
            acc[r][2] = ffma2(ha, wB0.x, acc[r][2]);
            acc[r][3] = ffma2(ha, wB0.y, acc[r][3]);
            acc[r][0] = ffma2(hb, wA1.x, acc[r][0]);
            acc[r][1] = ffma2(hb, wA1.y, acc[r][1]);
            acc[r][2] = ffma2(hb, wB1.x, acc[r][2]);
            acc[r][3] = ffma2(hb, wB1.y, acc[r][3]);
        }
    }
}

// ============================================================================
// Main: 74 clusters x 2 CTAs x 256 threads. Cluster owns 14 batch rows.
// CTA rank computes ALL K for its 128 duty gate-columns (N-split). K is split
// 2-way inside the CTA (kh = t>>7); partials combined via CTA-local SMEM.
// h is broadcast to the peer via DSMEM into parity double-buffers: writer
// targets buf pb^1 while readers use pb -> no WAR hazards by construction.
// ============================================================================
__global__ void __launch_bounds__(256, 1) __cluster_dims__(2, 1, 1)
lstm_main(const float* __restrict__ fcW,
          const float* __restrict__ fcb,
          float* __restrict__ out)
{
    extern __shared__ float sm[];
    float* sh0  = sm + OFF_H0;
    float* sh1  = sm + OFF_H1;
    float* sp   = sm + OFF_SP;
    float* sgx  = sm + OFF_GX;
    float* sb1  = sm + OFF_B1;
    float* sfc  = sm + OFF_FC;
    float* sfcb = sm + OFF_FCB;

    const int t = threadIdx.x;
    const unsigned rank = cluster_rank_();
    const unsigned peer = rank ^ 1u;
    const int cid  = blockIdx.x >> 1;
    const int b0   = (cid * B_) / NCL;
    const int cnt  = (((cid + 1) * B_) / NCL) - b0;
    const int duty = (int)rank * 128;
    const int jj   = t & 127;
    const int kh   = t >> 7;

    // ---------------- stage constants into SMEM ----------------------------
    for (int i = t; i < MBT * 128; i += 256) {
        const int r = i >> 7, u = i & 127;
        const int brow = b0 + (r < cnt ? r : cnt - 1);
        *(float4*)(sgx + i * 4) =
            *(const float4*)(g_gx0 + (brow * H_ + duty + u) * 4);
    }
    for (int i = t; i < 128; i += 256)
        *(float4*)(sb1 + i * 4) = *(const float4*)(g_b1 + (duty + i) * 4);
    for (int i = t; i < A_ * H_; i += 256) sfc[i] = fcW[i];
    if (t < A_) sfcb[t] = fcb[t];
    for (int i = t; i < HBUF; i += 256) { sh0[i] = 0.f; sh1[i] = 0.f; }  // buf 0

    const unsigned p_h0 = mapa_u32(smem_u32(sh0), peer);
    const unsigned p_h1 = mapa_u32(smem_u32(sh1), peer);

    float c0[MBT], c1[MBT];
    #pragma unroll
    for (int r = 0; r < MBT; r++) { c0[r] = 0.f; c1[r] = 0.f; }

    const float* w0base  = g_WT0p + (kh * 64) * 2048 + (duty + jj) * 8;
    const float* w1abase = g_WT1p + (kh * 64) * 2048 + (duty + jj) * 8;
    const float* w1bbase = g_WT1p + (128 + kh * 64) * 2048 + (duty + jj) * 8;
    const int hoff = kh * 128;

    __syncthreads();
    cluster_sync_();     // staging done in both CTAs (incl. peer SMEM ready)

    const float4 b1v = *(const float4*)(sb1 + jj * 4);

    int pb = 0;
    for (int step = 0; step < T_; step++) {
        // ================= layer 0: full-K GEMM on duty columns ============
        u64 acc[MBT][4];
        #pragma unroll
        for (int r = 0; r < MBT; r++)
            { acc[r][0] = 0; acc[r][1] = 0; acc[r][2] = 0; acc[r][3] = 0; }
        gemm_ns(w0base, sh0 + pb * HBUF + hoff, acc);

        if (kh) {           // upper K-half: publish partials
            #pragma unroll
            for (int r = 0; r < MBT; r++)
                *(float4*)(sp + (r * 128 + jj) * 4) =
                    make_float4(hadd2(acc[r][0]), hadd2(acc[r][1]),
                                hadd2(acc[r][2]), hadd2(acc[r][3]));
        }
        __syncthreads();
        if (!kh) {          // lower K-half: combine + cell0 + broadcast h0
            #pragma unroll
            for (int r = 0; r < MBT; r++) {
                const float4 pv = *(const float4*)(sp + (r * 128 + jj) * 4);
                const float4 gx = *(const float4*)(sgx + (r * 128 + jj) * 4);
                const float gi = hadd2(acc[r][0]) + pv.x + gx.x;
                const float gf = hadd2(acc[r][1]) + pv.y + gx.y;
                const float gg = hadd2(acc[r][2]) + pv.z + gx.z;
                const float go = hadd2(acc[r][3]) + pv.w + gx.w;
                const float cn = sigf(gf) * c0[r] + sigf(gi) * tanhf_(gg);
                c0[r] = cn;
                const float hv = sigf(go) * tanhf_(cn);
                const int off = (pb ^ 1) * HBUF + r * RS_ + duty + jj;
                sh0[off] = hv;
                st_dsmem_f(p_h0 + (unsigned)off * 4u, hv);
            }
        }
        cluster_sync_();    // h0_new (both halves) visible everywhere

        // ================= layer 1 =========================================
        #pragma unroll
        for (int r = 0; r < MBT; r++)
            { acc[r][0] = 0; acc[r][1] = 0; acc[r][2] = 0; acc[r][3] = 0; }
        gemm_ns(w1abase, sh0 + (pb ^ 1) * HBUF + hoff, acc);  // h0_new
        gemm_ns(w1bbase, sh1 + pb * HBUF + hoff, acc);        // h1_old

        if (kh) {
            #pragma unroll
            for (int r = 0; r < MBT; r++)
                *(float4*)(sp + (r * 128 + jj) * 4) =
                    make_float4(hadd2(acc[r][0]), hadd2(acc[r][1]),
                                hadd2(acc[r][2]), hadd2(acc[r][3]));
        }
        __syncthreads();
        if (!kh) {
            #pragma unroll
            for (int r = 0; r < MBT; r++) {
                const float4 pv = *(const float4*)(sp + (r * 128 + jj) * 4);
                const float gi = hadd2(acc[r][0]) + pv.x + b1v.x;
                const float gf = hadd2(acc[r][1]) + pv.y + b1v.y;
                const float gg = hadd2(acc[r][2]) + pv.z + b1v.z;
                const float go = hadd2(acc[r][3]) + pv.w + b1v.w;
                const float cn = sigf(gf) * c1[r] + sigf(gi) * tanhf_(gg);
                c1[r] = cn;
                const float hv = sigf(go) * tanhf_(cn);
                const int off = (pb ^ 1) * HBUF + r * RS_ + duty + jj;
                sh1[off] = hv;
                st_dsmem_f(p_h1 + (unsigned)off * 4u, hv);
            }
        }
        cluster_sync_();    // h1_new visible everywhere

        // ============ FC head: each rank outputs its 7 rows directly =======
        if (t < 56) {
            const int row = (int)rank * 7 + (t >> 3);   // cluster row 0..13
            const int a = t & 7;
            if (row < cnt) {
                const float* hrow = sh1 + (pb ^ 1) * HBUF + row * RS_;
                const float* wrow = sfc + a * H_;
                float f = 0.f;
                #pragma unroll 8
                for (int u = 0; u < H_; u++) f += hrow[u] * wrow[u];
                out[((b0 + row) * T_ + step) * A_ + a] = tanhf_(f + sfcb[a]);
            }
        }
        pb ^= 1;
    }
}

// ============================================================================
extern "C" void kernel_launch(void* const* d_in, const int* in_sizes, int n_in,
                              void* d_out, int out_size)
{
    const float* state = (const float*)d_in[0];
    const float* gamma = (const float*)d_in[1];
    const float* beta  = (const float*)d_in[2];
    const float* Wih0  = (const float*)d_in[3];
    const float* Whh0  = (const float*)d_in[4];
    const float* bih0  = (const float*)d_in[5];
    const float* bhh0  = (const float*)d_in[6];
    const float* Wih1  = (const float*)d_in[7];
    const float* Whh1  = (const float*)d_in[8];
    const float* bih1  = (const float*)d_in[9];
    const float* bhh1  = (const float*)d_in[10];
    const float* fcW   = (const float*)d_in[11];
    const float* fcb   = (const float*)d_in[12];
    float* out = (float*)d_out;

    // Host-side config, capture-safe, no static guards (rules: deterministic).
    cudaFuncSetAttribute(lstm_main,
                         cudaFuncAttributeMaxDynamicSharedMemorySize,
                         SMEM_BYTES);

    prep_weights<<<264, 256>>>(Whh0, Wih1, Whh1, bih1, bhh1);
    prep_gx0<<<B_, 256>>>(state, gamma, beta, Wih0, bih0, bhh0);
    lstm_main<<<GRID, 256, SMEM_BYTES>>>(fcW, fcb, out);
}

// round 12
// speedup vs baseline: 1.6207x; 1.4812x over previous
#include <cuda_runtime.h>
#include <cuda_fp16.h>
#include <cstdint>

#define T_   128
#define A_   8
#define CSZ  8
#define NCL  16
#define HTOT (NCL * 64 * 256)

// SMEM byte offsets (dynamic)
#define OFF_W0  0        // 128x256 fp16 swizzled (64KB)
#define OFF_W1  65536    // 128x512 fp16 swizzled (128KB)
#define OFF_H   196608   // 64x256 fp16 swizzled  (32KB)
#define OFF_FCW 229376   // 256 f32 (rank's action row)
#define OFF_B1  230400   // 128 f32
#define SMEMB   230912

__device__ __half g_W0img[CSZ * 128 * 256];
__device__ __half g_W1img[CSZ * 128 * 512];
__device__ __half g_h0[HTOT];
__device__ __half g_h1[2 * HTOT];
__device__ float  g_gx0[1024 * 1024];   // [b][unit*4+gate]
__device__ float  g_b1s[CSZ * 128];     // [rank][unit*4+gate]

// ---------------- helpers ---------------------------------------------------
__device__ __forceinline__ uint32_t s2u(const void* p) {
    uint32_t a;
    asm("{ .reg .u64 t; cvta.to.shared.u64 t, %1; cvt.u32.u64 %0, t; }"
        : "=r"(a) : "l"(p));
    return a;
}
__device__ __forceinline__ uint32_t crank() {
    uint32_t r; asm("mov.u32 %0, %%cluster_ctarank;" : "=r"(r)); return r;
}
__device__ __forceinline__ void csync() {
    asm volatile("barrier.cluster.arrive.aligned;" ::: "memory");
    asm volatile("barrier.cluster.wait.aligned;" ::: "memory");
}
__device__ __forceinline__ void fence_g() {
    asm volatile("membar.gl;" ::: "memory");
}
__device__ __forceinline__ float tap(float x) {
    float y; asm("tanh.approx.f32 %0, %1;" : "=f"(y) : "f"(x)); return y;
}
__device__ __forceinline__ float sg(float x) {
    return fmaf(tap(0.5f * x), 0.5f, 0.5f);
}
__device__ __forceinline__ void ldsm4(uint32_t (&d)[4], uint32_t addr) {
    asm volatile("ldmatrix.sync.aligned.m8n8.x4.shared.b16 {%0,%1,%2,%3}, [%4];"
        : "=r"(d[0]), "=r"(d[1]), "=r"(d[2]), "=r"(d[3]) : "r"(addr));
}
__device__ __forceinline__ void hmma(float (&c)[4], const uint32_t (&a)[4],
                                     uint32_t b0, uint32_t b1) {
    asm volatile(
        "mma.sync.aligned.m16n8k16.row.col.f32.f16.f16.f32 "
        "{%0,%1,%2,%3}, {%4,%5,%6,%7}, {%8,%9}, {%0,%1,%2,%3};"
        : "+f"(c[0]), "+f"(c[1]), "+f"(c[2]), "+f"(c[3])
        : "r"(a[0]), "r"(a[1]), "r"(a[2]), "r"(a[3]), "r"(b0), "r"(b1));
}

// one K=256 GEMM pass: A = sh (h, swizzled rows of 512B), B = weight image.
// rsh: log2 of B row bytes (9 for W0, 10 for W1). kofs: B k offset in halves.
__device__ __forceinline__ void gemm256(float (&acc)[8][4], uint32_t hsm,
                                        uint32_t wsm, int rsh, int kofs,
                                        int mt, int ch, int lane)
{
    const int arow = mt * 16 + ((lane >> 3) & 1) * 8 + (lane & 7);
    const uint32_t rbA = hsm + arow * 512;
    const uint32_t xrA = (uint32_t)((arow & 7) << 4);
    const uint32_t kaA = (uint32_t)(((lane >> 4) & 1) << 4);
    const int nb = ch * 64 + ((lane >> 4) & 1) * 8 + (lane & 7);
    const uint32_t xkB = (uint32_t)(((lane >> 3) & 1) << 4);
    #pragma unroll 2
    for (int kb = 0; kb < 16; kb++) {
        uint32_t a[4];
        ldsm4(a, rbA + ((kb * 32 + kaA) ^ xrA));
        #pragma unroll
        for (int nt = 0; nt < 4; nt++) {
            const int n = nb + nt * 16;
            uint32_t b[4];
            ldsm4(b, wsm + ((uint32_t)n << rsh) +
                     (((uint32_t)((kofs + kb * 16) * 2) + xkB) ^
                      (uint32_t)((n & 7) << 4)));
            hmma(acc[2 * nt],     a, b[0], b[1]);
            hmma(acc[2 * nt + 1], a, b[2], b[3]);
        }
    }
}

// ============================================================================
__global__ void prep_weights(const float* __restrict__ Whh0,
                             const float* __restrict__ Wih1,
                             const float* __restrict__ Whh1,
                             const float* __restrict__ bih1,
                             const float* __restrict__ bhh1)
{
    const int idx = blockIdx.x * blockDim.x + threadIdx.x;
    const int str = gridDim.x * blockDim.x;
    for (int i = idx; i < CSZ * 128 * 256; i += str) {
        const int rk = i >> 15, n = (i >> 8) & 127, k = i & 255;
        const int no = (n & 3) * 256 + rk * 32 + (n >> 2);
        g_W0img[(rk << 15) + (n << 8) + (k ^ ((n & 7) << 3))] =
            __float2half(Whh0[no * 256 + k]);
    }
    for (int i = idx; i < CSZ * 128 * 512; i += str) {
        const int rk = i >> 16, n = (i >> 9) & 127, k = i & 511;
        const int no = (n & 3) * 256 + rk * 32 + (n >> 2);
        const float v = (k < 256) ? Wih1[no * 256 + k]
                                  : Whh1[no * 256 + (k - 256)];
        g_W1img[(rk << 16) + (n << 9) + (k ^ ((n & 7) << 3))] = __float2half(v);
    }
    for (int i = idx; i < CSZ * 128; i += str) {
        const int rk = i >> 7, cc = i & 127;
        const int no = (cc & 3) * 256 + rk * 32 + (cc >> 2);
        g_b1s[i] = bih1[no] + bhh1[no];
    }
    for (int i = idx; i < 2 * HTOT; i += str) g_h1[i] = __half(0.0f);
}

__global__ void prep_gx0(const float* __restrict__ state,
                         const float* __restrict__ gamma,
                         const float* __restrict__ beta,
                         const float* __restrict__ Wih0,
                         const float* __restrict__ bih0,
                         const float* __restrict__ bhh0)
{
    const int b = blockIdx.x, t = threadIdx.x;
    __shared__ float xs[64], xn[64];
    if (t < 64) xs[t] = state[b * 64 + t];
    __syncthreads();
    float mu = 0.f;
    #pragma unroll
    for (int k = 0; k < 64; k++) mu += xs[k];
    mu *= (1.0f / 64.0f);
    float var = 0.f;
    #pragma unroll
    for (int k = 0; k < 64; k++) { const float d = xs[k] - mu; var += d * d; }
    const float rs = rsqrtf(var * (1.0f / 64.0f) + 1e-5f);
    if (t < 64) xn[t] = (xs[t] - mu) * rs * gamma[t] + beta[t];
    __syncthreads();
    #pragma unroll
    for (int g = 0; g < 4; g++) {
        const int n = g * 256 + t;
        const float* w = Wih0 + n * 64;
        float acc = bih0[n] + bhh0[n];
        #pragma unroll
        for (int k = 0; k < 64; k++) acc += xn[k] * w[k];
        g_gx0[b * 1024 + t * 4 + g] = acc;
    }
}

// ============================================================================
// Main: 16 clusters x 8 CTAs x 256 thr. Cluster = 64 batch rows; CTA rank =
// 128 gate cols (32 units). Weights fp16 SMEM-resident; gates via HMMA; cell
// in regs; h exchanged via L2 + cluster barriers (parity-buffered h1).
// ============================================================================
__global__ void __launch_bounds__(256, 1) __cluster_dims__(CSZ, 1, 1)
lstm_mma(const float* __restrict__ fcW, const float* __restrict__ fcb,
         float* __restrict__ out)
{
    extern __shared__ char sm[];
    float* sfcw = (float*)(sm + OFF_FCW);
    float* sb1  = (float*)(sm + OFF_B1);
    const uint32_t w0sm = s2u(sm) + OFF_W0;
    const uint32_t w1sm = s2u(sm) + OFF_W1;
    const uint32_t hsm  = s2u(sm) + OFF_H;

    const int tid = threadIdx.x, wid = tid >> 5, lane = tid & 31;
    const int mt = wid & 3, ch = wid >> 2;
    const uint32_t rank = crank();
    const int cid = blockIdx.x >> 3;

    {   // stage weights + constants
        const uint4* s0 = (const uint4*)(g_W0img + ((uint32_t)rank << 15));
        const uint4* s1 = (const uint4*)(g_W1img + ((uint32_t)rank << 16));
        uint4* d0 = (uint4*)sm;
        uint4* d1 = (uint4*)(sm + OFF_W1);
        for (int i = tid; i < 4096; i += 256) d0[i] = s0[i];
        for (int i = tid; i < 8192; i += 256) d1[i] = s1[i];
        for (int i = tid; i < 256; i += 256) sfcw[i] = fcW[rank * 256 + i];
        if (tid < 128) sb1[tid] = g_b1s[rank * 128 + tid];
        uint4 z = make_uint4(0, 0, 0, 0);
        for (int i = tid; i < 2048; i += 256) ((uint4*)(sm + OFF_H))[i] = z;
    }
    const float fcbv = fcb[rank];

    // per-lane cell geometry
    const int cellrow = mt * 16 + (lane >> 2) + ((lane & 1) << 3);
    const int grow = cid * 64 + cellrow;
    const int uloc0 = ch * 16 + ((lane >> 1) & 1);
    float4 gx[8];
    #pragma unroll
    for (int t = 0; t < 8; t++)
        gx[t] = *(const float4*)(g_gx0 + grow * 1024 +
                                 ((int)rank * 32 + uloc0 + 2 * t) * 4);
    float c0r[8], c1r[8];
    #pragma unroll
    for (int t = 0; t < 8; t++) { c0r[t] = 0.f; c1r[t] = 0.f; }

    __half* h0st = g_h0 + grow * 256 + (int)rank * 32 + uloc0;
    const int lr = tid >> 2, lseg = tid & 3;
    const uint4* h0ld = (const uint4*)(g_h0 + (cid * 64 + lr) * 256 + lseg * 64);

    __syncthreads();

    uint4 hreg[8];
    float acc[8][4];

    for (int s = 0; s < T_; s++) {
        // ---- L0 MMA: gates0 = h0(s-1) @ W0 -------------------------------
        #pragma unroll
        for (int t = 0; t < 8; t++)
            { acc[t][0] = 0.f; acc[t][1] = 0.f; acc[t][2] = 0.f; acc[t][3] = 0.f; }
        gemm256(acc, hsm, w0sm, 9, 0, mt, ch, lane);
        // ---- cell0 -> STG h0(s) -------------------------------------------
        #pragma unroll
        for (int t = 0; t < 8; t++) {
            const float s0 = __shfl_xor_sync(0xffffffffu, acc[t][0], 1);
            const float s1 = __shfl_xor_sync(0xffffffffu, acc[t][1], 1);
            const float s2 = __shfl_xor_sync(0xffffffffu, acc[t][2], 1);
            const float s3 = __shfl_xor_sync(0xffffffffu, acc[t][3], 1);
            float gi, gf, gg, go;
            if (lane & 1) { gi = s2; gf = s3; gg = acc[t][2]; go = acc[t][3]; }
            else          { gi = acc[t][0]; gf = acc[t][1]; gg = s0; go = s1; }
            gi += gx[t].x; gf += gx[t].y; gg += gx[t].z; go += gx[t].w;
            const float cn = sg(gf) * c0r[t] + sg(gi) * tap(gg);
            c0r[t] = cn;
            h0st[2 * t] = __float2half(sg(go) * tap(cn));
        }
        fence_g();
        csync();                                 // CS1: h0(s) visible
        fence_g();
        // ---- load full h0(s) -> hreg -> sh --------------------------------
        #pragma unroll
        for (int i = 0; i < 8; i++) hreg[i] = h0ld[i];
        #pragma unroll
        for (int i = 0; i < 8; i++)
            *(uint4*)(sm + OFF_H + lr * 512 +
                      ((lseg * 128 + i * 16) ^ ((lr & 7) << 4))) = hreg[i];
        __syncthreads();
        // ---- L1 part A: h0(s) @ W1[:, 0:256] ------------------------------
        #pragma unroll
        for (int t = 0; t < 8; t++)
            { acc[t][0] = 0.f; acc[t][1] = 0.f; acc[t][2] = 0.f; acc[t][3] = 0.f; }
        gemm256(acc, hsm, w1sm, 10, 0, mt, ch, lane);
        __syncthreads();
        // ---- load h1(s-1), FC(s-1), stage h1 into sh ----------------------
        {
            const uint4* h1ld = (const uint4*)(g_h1 + ((s & 1) ^ 1) * HTOT +
                                               (cid * 64 + lr) * 256 + lseg * 64);
            uint4 t1[8];
            #pragma unroll
            for (int i = 0; i < 8; i++) t1[i] = h1ld[i];
            if (s > 0) {
                float f = 0.f;
                #pragma unroll
                for (int i = 0; i < 8; i++) {
                    const __half2* hp = (const __half2*)&t1[i];
                    #pragma unroll
                    for (int j = 0; j < 4; j++) {
                        const float2 h2 = __half22float2(hp[j]);
                        const int kk = lseg * 64 + i * 8 + 2 * j;
                        f += h2.x * sfcw[kk] + h2.y * sfcw[kk + 1];
                    }
                }
                f += __shfl_xor_sync(0xffffffffu, f, 1);
                f += __shfl_xor_sync(0xffffffffu, f, 2);
                if ((tid & 3) == 0)
                    out[((cid * 64 + lr) * T_ + (s - 1)) * A_ + rank] =
                        tap(f + fcbv);
            }
            #pragma unroll
            for (int i = 0; i < 8; i++)
                *(uint4*)(sm + OFF_H + lr * 512 +
                          ((lseg * 128 + i * 16) ^ ((lr & 7) << 4))) = t1[i];
        }
        __syncthreads();
        // ---- L1 part B: h1(s-1) @ W1[:, 256:512] --------------------------
        gemm256(acc, hsm, w1sm, 10, 256, mt, ch, lane);
        // ---- cell1 -> STG h1(s) (parity buffer) ---------------------------
        __half* h1st = g_h1 + (s & 1) * HTOT + grow * 256 +
                       (int)rank * 32 + uloc0;
        #pragma unroll
        for (int t = 0; t < 8; t++) {
            const float s0 = __shfl_xor_sync(0xffffffffu, acc[t][0], 1);
            const float s1 = __shfl_xor_sync(0xffffffffu, acc[t][1], 1);
            const float s2 = __shfl_xor_sync(0xffffffffu, acc[t][2], 1);
            const float s3 = __shfl_xor_sync(0xffffffffu, acc[t][3], 1);
            float gi, gf, gg, go;
            if (lane & 1) { gi = s2; gf = s3; gg = acc[t][2]; go = acc[t][3]; }
            else          { gi = acc[t][0]; gf = acc[t][1]; gg = s0; go = s1; }
            const float4 bv = *(const float4*)(sb1 + (uloc0 + 2 * t) * 4);
            gi += bv.x; gf += bv.y; gg += bv.z; go += bv.w;
            const float cn = sg(gf) * c1r[t] + sg(gi) * tap(gg);
            c1r[t] = cn;
            h1st[2 * t] = __float2half(sg(go) * tap(cn));
        }
        fence_g();
        csync();                                 // CS2: h1(s) visible
        fence_g();
        // ---- restore h0(s) into sh for next L0 ----------------------------
        #pragma unroll
        for (int i = 0; i < 8; i++)
            *(uint4*)(sm + OFF_H + lr * 512 +
                      ((lseg * 128 + i * 16) ^ ((lr & 7) << 4))) = hreg[i];
        __syncthreads();
    }

    // final FC for step 127 (h1(127) in parity buf 1)
    {
        const uint4* h1ld = (const uint4*)(g_h1 + 1 * HTOT +
                                           (cid * 64 + lr) * 256 + lseg * 64);
        float f = 0.f;
        #pragma unroll
        for (int i = 0; i < 8; i++) {
            const uint4 v = h1ld[i];
            const __half2* hp = (const __half2*)&v;
            #pragma unroll
            for (int j = 0; j < 4; j++) {
                const float2 h2 = __half22float2(hp[j]);
                const int kk = lseg * 64 + i * 8 + 2 * j;
                f += h2.x * sfcw[kk] + h2.y * sfcw[kk + 1];
            }
        }
        f += __shfl_xor_sync(0xffffffffu, f, 1);
        f += __shfl_xor_sync(0xffffffffu, f, 2);
        if ((tid & 3) == 0)
            out[((cid * 64 + lr) * T_ + 127) * A_ + rank] = tap(f + fcbv);
    }
}

// ============================================================================
extern "C" void kernel_launch(void* const* d_in, const int* in_sizes, int n_in,
                              void* d_out, int out_size)
{
    const float* state = (const float*)d_in[0];
    const float* gamma = (const float*)d_in[1];
    const float* beta  = (const float*)d_in[2];
    const float* Wih0  = (const float*)d_in[3];
    const float* Whh0  = (const float*)d_in[4];
    const float* bih0  = (const float*)d_in[5];
    const float* bhh0  = (const float*)d_in[6];
    const float* Wih1  = (const float*)d_in[7];
    const float* Whh1  = (const float*)d_in[8];
    const float* bih1  = (const float*)d_in[9];
    const float* bhh1  = (const float*)d_in[10];
    const float* fcW   = (const float*)d_in[11];
    const float* fcb   = (const float*)d_in[12];
    float* out = (float*)d_out;

    cudaFuncSetAttribute(lstm_mma, cudaFuncAttributeMaxDynamicSharedMemorySize,
                         SMEMB);
    prep_weights<<<264, 256>>>(Whh0, Wih1, Whh1, bih1, bhh1);
    prep_gx0<<<1024, 256>>>(state, gamma, beta, Wih0, bih0, bhh0);
    lstm_mma<<<NCL * CSZ, 256, SMEMB>>>(fcW, fcb, out);
}